// round 16
// baseline (speedup 1.0000x reference)
#include <cuda_runtime.h>
#include <cuda_bf16.h>
#include <cstdint>

#define S 3072
#define DIM 1536
#define H 12
#define NB 24
#define SCALE 0.08838834764831845f   // 1/sqrt(128)
#define NEG_BIG (-1e30f)
#define NPAIR (H * NB)                // 288

// ---------------- scratch (device globals; no allocation allowed) ----------
__device__ float g_q[S * DIM];
__device__ float g_k[S * DIM];
__device__ float g_v[S * DIM];
__device__ float g_qw[NB * DIM];
__device__ float g_kw[NB * DIM];
__device__ int   g_list[H * NB * NB];
__device__ int   g_cnt[NPAIR];
__device__ int   g_order[NPAIR];

// bf16 hi/lo splits
__device__ __nv_bfloat16 s_xh[S * DIM],  s_xl[S * DIM];
__device__ __nv_bfloat16 s_ah[S * DIM],  s_al[S * DIM];
__device__ __nv_bfloat16 s_wqh[DIM * DIM], s_wql[DIM * DIM];
__device__ __nv_bfloat16 s_wkh[DIM * DIM], s_wkl[DIM * DIM];
__device__ __nv_bfloat16 s_wvh[DIM * DIM], s_wvl[DIM * DIM];
__device__ __nv_bfloat16 s_woh[DIM * DIM], s_wol[DIM * DIM];
__device__ __nv_bfloat16 s_qh[S * DIM], s_ql[S * DIM];
__device__ __nv_bfloat16 s_kh[S * DIM], s_kl[S * DIM];
__device__ __nv_bfloat16 s_vth[DIM * S], s_vtl[DIM * S];   // transposed [d][t]

// ---------------------------------------------------------------------------
__device__ __forceinline__ uint32_t smem_u32(const void* p) {
    uint32_t a;
    asm("{ .reg .u64 t; cvta.to.shared.u64 t, %1; cvt.u32.u64 %0, t; }"
        : "=r"(a) : "l"(p));
    return a;
}
__device__ __forceinline__ void cp16(uint32_t dst, const void* src) {
    asm volatile("cp.async.cg.shared.global [%0], [%1], 16;" :: "r"(dst), "l"(src));
}
#define CP_COMMIT() asm volatile("cp.async.commit_group;" ::: "memory")
#define CP_WAIT(n)  asm volatile("cp.async.wait_group %0;" :: "n"(n) : "memory")

__device__ __forceinline__ void mma_bf16(float* c, uint32_t a0, uint32_t a1,
                                         uint32_t a2, uint32_t a3,
                                         uint32_t b0, uint32_t b1) {
    asm volatile(
        "mma.sync.aligned.m16n8k16.row.col.f32.bf16.bf16.f32 "
        "{%0,%1,%2,%3}, {%4,%5,%6,%7}, {%8,%9}, {%0,%1,%2,%3};"
        : "+f"(c[0]), "+f"(c[1]), "+f"(c[2]), "+f"(c[3])
        : "r"(a0), "r"(a1), "r"(a2), "r"(a3), "r"(b0), "r"(b1));
}
__device__ __forceinline__ void ldsm_x4(uint32_t& r0, uint32_t& r1,
                                        uint32_t& r2, uint32_t& r3, uint32_t a) {
    asm volatile("ldmatrix.sync.aligned.m8n8.x4.shared.b16 {%0,%1,%2,%3}, [%4];"
                 : "=r"(r0), "=r"(r1), "=r"(r2), "=r"(r3) : "r"(a));
}
__device__ __forceinline__ uint32_t pack2(float x, float y) {
    __nv_bfloat162 t = __floats2bfloat162_rn(x, y);
    return *(uint32_t*)&t;
}

// ---------------------------------------------------------------------------
// split: fp32 -> (bf16 hi, bf16 lo), 4 elems/thread vectorized
// ---------------------------------------------------------------------------
__global__ __launch_bounds__(256) void split_kernel(
    const float* __restrict__ X, __nv_bfloat16* __restrict__ Hh,
    __nv_bfloat16* __restrict__ Hl)
{
    int i = (blockIdx.x * 256 + threadIdx.x) * 4;
    float4 v = *(const float4*)(X + i);
    uint32_t h0 = pack2(v.x, v.y), h1 = pack2(v.z, v.w);
    __nv_bfloat162 b0 = *(__nv_bfloat162*)&h0;
    __nv_bfloat162 b1 = *(__nv_bfloat162*)&h1;
    uint32_t l0 = pack2(v.x - __bfloat162float(b0.x), v.y - __bfloat162float(b0.y));
    uint32_t l1 = pack2(v.z - __bfloat162float(b1.x), v.w - __bfloat162float(b1.y));
    *(uint32_t*)(Hh + i) = h0;  *(uint32_t*)(Hh + i + 2) = h1;
    *(uint32_t*)(Hl + i) = l0;  *(uint32_t*)(Hl + i + 2) = l1;
}

// ---------------------------------------------------------------------------
__global__ __launch_bounds__(256) void vt_split(
    const float* __restrict__ V, __nv_bfloat16* __restrict__ Th,
    __nv_bfloat16* __restrict__ Tl)
{
    __shared__ float tile[32][33];
    const int t0 = blockIdx.x * 32, d0 = blockIdx.y * 32;
    const int tx = threadIdx.x & 31, ty = threadIdx.x >> 5;
#pragma unroll
    for (int i = 0; i < 4; i++)
        tile[ty + 8 * i][tx] = V[(size_t)(t0 + ty + 8 * i) * DIM + d0 + tx];
    __syncthreads();
#pragma unroll
    for (int i = 0; i < 4; i++) {
        float v = tile[tx][ty + 8 * i];
        __nv_bfloat16 h = __float2bfloat16(v);
        size_t o = (size_t)(d0 + ty + 8 * i) * S + t0 + tx;
        Th[o] = h;
        Tl[o] = __float2bfloat16(v - __bfloat162float(h));
    }
}

// ---------------------------------------------------------------------------
// mma.sync GEMM, bf16-split 3-product; 256x128 CTA tile, 512 thr, 2-stage.
// Warp tile 64m x 32n; minimal-ldsm ordering (B frags resident per ks).
// ---------------------------------------------------------------------------
#define GTILEA 36864                  // 256 rows * 144B
#define GTILEB 18432                  // 128 rows * 144B
#define GSTAGE (2 * GTILEA + 2 * GTILEB)   // 110592
#define GEMM_SMEM (2 * GSTAGE)             // 221184

__global__ __launch_bounds__(512, 1) void gemm_mma(
    const __nv_bfloat16* __restrict__ Ah, const __nv_bfloat16* __restrict__ Al,
    const __nv_bfloat16* __restrict__ Wh0, const __nv_bfloat16* __restrict__ Wl0,
    const __nv_bfloat16* __restrict__ Wh1, const __nv_bfloat16* __restrict__ Wl1,
    const __nv_bfloat16* __restrict__ Wh2, const __nv_bfloat16* __restrict__ Wl2,
    const float* __restrict__ b0, const float* __restrict__ b1,
    const float* __restrict__ b2,
    float* __restrict__ C0, float* __restrict__ C1, float* __restrict__ C2)
{
    extern __shared__ char smem[];
    const int z = blockIdx.z;
    const __nv_bfloat16* Wh = z == 0 ? Wh0 : (z == 1 ? Wh1 : Wh2);
    const __nv_bfloat16* Wl = z == 0 ? Wl0 : (z == 1 ? Wl1 : Wl2);
    const float* bias = z == 0 ? b0 : (z == 1 ? b1 : b2);
    float* C = z == 0 ? C0 : (z == 1 ? C1 : C2);

    const int n0 = blockIdx.x * 128;
    const int m0 = blockIdx.y * 256;
    const int tid = threadIdx.x;
    const int lane = tid & 31, wid = tid >> 5;
    const int warp_m = wid & 3, warp_n = wid >> 2;   // 4 x 4 warps
    const int g = lane >> 2, th = lane & 3;
    const int lidx = lane >> 3, lrow = lane & 7;

    const uint32_t sbase = smem_u32(smem);
    const uint32_t ga_off = (uint32_t)(warp_m * 64 + lrow + ((lane >> 3) & 1) * 8) * 144
                          + ((lane >> 4) & 1) * 16;
    const uint32_t gb_off = (uint32_t)(warp_n * 32 + lrow + (lidx >> 1) * 8) * 144
                          + (lidx & 1) * 16;

    auto load_stage = [&](int stage, int c) {
        uint32_t stb = sbase + stage * GSTAGE;
        const __nv_bfloat16* ah = Ah + (size_t)m0 * DIM + c * 64;
        const __nv_bfloat16* al = Al + (size_t)m0 * DIM + c * 64;
        const __nv_bfloat16* wh = Wh + (size_t)n0 * DIM + c * 64;
        const __nv_bfloat16* wl = Wl + (size_t)n0 * DIM + c * 64;
#pragma unroll
        for (int u = 0; u < 4; u++) {           // A: 256 rows x 8 segs = 2048
            int f = tid + 512 * u;
            int row = f >> 3, seg = f & 7;
            cp16(stb + row * 144 + seg * 16, ah + (size_t)row * DIM + seg * 8);
            cp16(stb + GTILEA + row * 144 + seg * 16, al + (size_t)row * DIM + seg * 8);
        }
#pragma unroll
        for (int u = 0; u < 2; u++) {           // W: 128 rows x 8 segs = 1024
            int f = tid + 512 * u;
            int row = f >> 3, seg = f & 7;
            cp16(stb + 2 * GTILEA + row * 144 + seg * 16, wh + (size_t)row * DIM + seg * 8);
            cp16(stb + 2 * GTILEA + GTILEB + row * 144 + seg * 16, wl + (size_t)row * DIM + seg * 8);
        }
    };

    float acc[4][4][4];
#pragma unroll
    for (int i = 0; i < 4; i++)
#pragma unroll
        for (int j = 0; j < 4; j++)
#pragma unroll
            for (int r = 0; r < 4; r++) acc[i][j][r] = 0.f;

    load_stage(0, 0); CP_COMMIT();

    for (int c = 0; c < 24; c++) {
        if (c + 1 < 24) { load_stage((c + 1) & 1, c + 1); CP_COMMIT(); CP_WAIT(1); }
        else            { CP_WAIT(0); }
        __syncthreads();

        const uint32_t stg = sbase + (c & 1) * GSTAGE;
        const uint32_t sAh = stg, sAl = stg + GTILEA;
        const uint32_t sWh = stg + 2 * GTILEA, sWl = stg + 2 * GTILEA + GTILEB;

#pragma unroll
        for (int ks = 0; ks < 4; ks++) {
            uint32_t bh[8], bl[8];
            ldsm_x4(bh[0], bh[1], bh[2], bh[3], sWh + gb_off + ks * 32);
            ldsm_x4(bh[4], bh[5], bh[6], bh[7], sWh + gb_off + 2304 + ks * 32);
            ldsm_x4(bl[0], bl[1], bl[2], bl[3], sWl + gb_off + ks * 32);
            ldsm_x4(bl[4], bl[5], bl[6], bl[7], sWl + gb_off + 2304 + ks * 32);
#pragma unroll
            for (int mt = 0; mt < 4; mt++) {
                uint32_t a0, a1, a2, a3, c0, c1, c2, c3;
                ldsm_x4(a0, a1, a2, a3, sAh + ga_off + mt * 2304 + ks * 32);
                ldsm_x4(c0, c1, c2, c3, sAl + ga_off + mt * 2304 + ks * 32);
#pragma unroll
                for (int j = 0; j < 4; j++) {
                    mma_bf16(acc[mt][j], a0, a1, a2, a3, bh[2 * j], bh[2 * j + 1]);
                    mma_bf16(acc[mt][j], a0, a1, a2, a3, bl[2 * j], bl[2 * j + 1]);
                    mma_bf16(acc[mt][j], c0, c1, c2, c3, bh[2 * j], bh[2 * j + 1]);
                }
            }
        }
        __syncthreads();
    }

#pragma unroll
    for (int mt = 0; mt < 4; mt++) {
        int r = m0 + warp_m * 64 + mt * 16 + g;
#pragma unroll
        for (int j = 0; j < 4; j++) {
            int col = n0 + warp_n * 32 + j * 8 + th * 2;
            float bx = bias[col], by = bias[col + 1];
            float2 o0 = { acc[mt][j][0] + bx, acc[mt][j][1] + by };
            float2 o1 = { acc[mt][j][2] + bx, acc[mt][j][3] + by };
            *(float2*)(C + (size_t)r * DIM + col) = o0;
            *(float2*)(C + (size_t)(r + 8) * DIM + col) = o1;
        }
    }
}

// ---------------------------------------------------------------------------
// RMSNorm + RoPE, fused bf16 hi/lo split output
// ---------------------------------------------------------------------------
__global__ __launch_bounds__(256) void norm_rope_kernel(
    float* __restrict__ Xq, float* __restrict__ Xk,
    __nv_bfloat16* __restrict__ Qh, __nv_bfloat16* __restrict__ Ql,
    __nv_bfloat16* __restrict__ Kh, __nv_bfloat16* __restrict__ Kl,
    const float* __restrict__ gq, const float* __restrict__ gk,
    const float* __restrict__ fc, const float* __restrict__ fs)
{
    const int s = blockIdx.x;
    float* X = blockIdx.y ? Xk : Xq;
    __nv_bfloat16* Oh = blockIdx.y ? Kh : Qh;
    __nv_bfloat16* Ol = blockIdx.y ? Kl : Ql;
    const float* g = blockIdx.y ? gk : gq;
    float* row = X + (size_t)s * 1536;
    const int tid = threadIdx.x;

    float ss = 0.f;
#pragma unroll
    for (int c = 0; c < 6; c++) {
        float v = row[tid + 256 * c];
        ss += v * v;
    }
#pragma unroll
    for (int o = 16; o >= 1; o >>= 1)
        ss += __shfl_xor_sync(0xffffffffu, ss, o);
    __shared__ float red[8];
    if ((tid & 31) == 0) red[tid >> 5] = ss;
    __syncthreads();
    float tot = 0.f;
#pragma unroll
    for (int w = 0; w < 8; w++) tot += red[w];
    float scale = rsqrtf(tot * (1.f / 1536.f) + 1e-5f);

#pragma unroll
    for (int u = 0; u < 3; u++) {
        int p = tid + 256 * u;
        int i = p & 63;
        float c = fc[s * 64 + i];
        float sn = fs[s * 64 + i];
        float x0 = row[2 * p] * scale * g[2 * p];
        float x1 = row[2 * p + 1] * scale * g[2 * p + 1];
        float y0 = x0 * c - x1 * sn;
        float y1 = x0 * sn + x1 * c;
        row[2 * p]     = y0;
        row[2 * p + 1] = y1;
        size_t o = (size_t)s * 1536 + 2 * p;
        __nv_bfloat16 h0 = __float2bfloat16(y0);
        __nv_bfloat16 h1 = __float2bfloat16(y1);
        Oh[o] = h0;     Oh[o + 1] = h1;
        Ol[o] = __float2bfloat16(y0 - __bfloat162float(h0));
        Ol[o + 1] = __float2bfloat16(y1 - __bfloat162float(h1));
    }
}

// ---------------------------------------------------------------------------
__global__ __launch_bounds__(256) void pool_mean(
    const float* __restrict__ Q, const float* __restrict__ Kx,
    float* __restrict__ qw, float* __restrict__ kw)
{
    const int nb = blockIdx.x;
    const float* X = blockIdx.y ? Kx : Q;
    float* Wo = blockIdx.y ? kw : qw;
    const int tid = threadIdx.x;
    float acc[6] = {0, 0, 0, 0, 0, 0};
    for (int t = 0; t < 128; t++) {
        const float* row = X + (size_t)(nb * 128 + t) * 1536;
#pragma unroll
        for (int c = 0; c < 6; c++) acc[c] += row[tid + 256 * c];
    }
#pragma unroll
    for (int c = 0; c < 6; c++)
        Wo[nb * 1536 + tid + 256 * c] = acc[c] * (1.f / 128.f);
}

// ---------------------------------------------------------------------------
// select_blocks: fused draft scores + row softmax + per-head top-k threshold
// + list build. grid = H, 576 threads (one per (l, m)).
// ---------------------------------------------------------------------------
__global__ __launch_bounds__(576) void select_blocks(
    const float* __restrict__ qw, const float* __restrict__ kw,
    int* __restrict__ list, int* __restrict__ cnt)
{
    const int h = blockIdx.x;
    __shared__ float qb[24 * 128];
    __shared__ float kb[24 * 128];
    __shared__ float sbuf[576];
    __shared__ float battn[576];
    __shared__ float result;
    const int tid = threadIdx.x;
    const int l = tid / 24, m = tid % 24;

    for (int i = tid; i < 24 * 128; i += 576) {
        int r = i >> 7, d = i & 127;
        qb[i] = qw[r * 1536 + h * 128 + d];
        kb[i] = kw[r * 1536 + h * 128 + d];
    }
    if (tid == 0) result = 0.f;
    __syncthreads();

    int rl = l >> 2, cl = l & 3, rm = m >> 2, cm = m & 3;
    bool ok = (rm >= rl - 3) && (rm <= rl + 2) && (cm >= cl - 3) && (cm <= cl + 2);
    float sc = NEG_BIG;
    if (ok) {
        float sum = 0.f;
        const float* qr = qb + l * 128;
        const float* kr = kb + m * 128;
#pragma unroll 8
        for (int d = 0; d < 128; d++) sum += qr[d] * kr[d];
        sc = sum * SCALE;
    }
    sbuf[tid] = sc;
    __syncthreads();

    float mx = NEG_BIG;
#pragma unroll
    for (int j = 0; j < 24; j++) mx = fmaxf(mx, sbuf[l * 24 + j]);
    float e = __expf(sc - mx);
    battn[tid] = e;
    __syncthreads();
    float se = 0.f;
#pragma unroll
    for (int j = 0; j < 24; j++) se += battn[l * 24 + j];
    __syncthreads();
    float p = e / se;
    battn[tid] = p;
    __syncthreads();

    // threshold = 129th largest (with tie counting identical to sorted top-k)
    {
        int cg = 0, ce = 0;
        for (int x = 0; x < 576; x++) {
            cg += (battn[x] > p);
            ce += (battn[x] == p);
        }
        if (cg <= 128 && cg + ce >= 129) result = p;
    }
    __syncthreads();
    float thr = result;

    if (tid < 24) {      // tid = l
        int pos = 0;
        for (int mm = 0; mm < 24; mm++) {
            if (battn[tid * 24 + mm] > thr)
                list[(h * 24 + tid) * 24 + pos++] = mm;
        }
        cnt[h * 24 + tid] = pos;
    }
}

// ---------------------------------------------------------------------------
__global__ void order_pairs(const int* __restrict__ cnt, int* __restrict__ order)
{
    __shared__ int bucket[32];
    __shared__ int base[32];
    const int tid = threadIdx.x;
    if (tid < 32) bucket[tid] = 0;
    __syncthreads();
    int nc = cnt[tid];
    atomicAdd(&bucket[nc], 1);
    __syncthreads();
    if (tid == 0) {
        int acc = 0;
        for (int v = 31; v >= 0; v--) { base[v] = acc; acc += bucket[v]; }
    }
    __syncthreads();
    int pos = atomicAdd(&base[nc], 1);
    order[pos] = tid;
}

// ---------------------------------------------------------------------------
// Block-sparse flash attention: mma.sync + ldmatrix, Q frags in registers,
// software-pipelined K/V loads. (proven R15)
// ---------------------------------------------------------------------------
#define AT_U32 68
#define AT_TILEB (128 * AT_U32 * 4)     // 34816
#define ATT_SMEM (6 * AT_TILEB)         // 208896

__global__ __launch_bounds__(256, 1) void attn_mma(
    const __nv_bfloat16* __restrict__ Qh, const __nv_bfloat16* __restrict__ Ql,
    const __nv_bfloat16* __restrict__ Kh, const __nv_bfloat16* __restrict__ Kl,
    const __nv_bfloat16* __restrict__ Vth, const __nv_bfloat16* __restrict__ Vtl,
    const int* __restrict__ list, const int* __restrict__ cnt,
    const int* __restrict__ order,
    __nv_bfloat16* __restrict__ OAh, __nv_bfloat16* __restrict__ OAl)
{
    extern __shared__ char smem[];
    const int pair = order[blockIdx.x];
    const int h = pair / 24, l = pair % 24;
    const int tid = threadIdx.x;
    const int lane = tid & 31, wid = tid >> 5;
    const int g = lane >> 2, th = lane & 3;
    const int lidx = lane >> 3, lrow = lane & 7;
    const uint32_t sb = smem_u32(smem);
    const uint32_t T0 = sb,               T1 = sb + AT_TILEB;
    const uint32_t T2 = sb + 2 * AT_TILEB, T3 = sb + 3 * AT_TILEB;
    const uint32_t T4 = sb + 4 * AT_TILEB, T5 = sb + 5 * AT_TILEB;

    const uint32_t a_off = (uint32_t)(wid * 16 + lrow + ((lane >> 3) & 1) * 8) * 272
                         + ((lane >> 4) & 1) * 16;
    const uint32_t b_off = (uint32_t)(lrow + (lidx >> 1) * 8) * 272 + (lidx & 1) * 16;

    // ---- stage Q into T0/T1, pull fragments into registers ----
#pragma unroll
    for (int t = 0; t < 2; t++) {
        const __nv_bfloat16* src = t ? Ql : Qh;
        uint32_t dst = t ? T1 : T0;
#pragma unroll
        for (int u = 0; u < 8; u++) {
            int f = tid + 256 * u;
            int row = f >> 4, seg = f & 15;
            cp16(dst + row * 272 + seg * 16,
                 src + (size_t)(l * 128 + row) * DIM + h * 128 + seg * 8);
        }
    }
    CP_COMMIT();
    CP_WAIT(0);
    __syncthreads();

    uint32_t qfh[8][4], qfl[8][4];
#pragma unroll
    for (int ks = 0; ks < 8; ks++) {
        ldsm_x4(qfh[ks][0], qfh[ks][1], qfh[ks][2], qfh[ks][3], T0 + a_off + ks * 32);
        ldsm_x4(qfl[ks][0], qfl[ks][1], qfl[ks][2], qfl[ks][3], T1 + a_off + ks * 32);
    }
    __syncthreads();

    const int nc = cnt[pair];

    auto load_K = [&](int mb, uint32_t dh, uint32_t dl) {
#pragma unroll
        for (int u = 0; u < 8; u++) {
            int f = tid + 256 * u;
            int row = f >> 4, seg = f & 15;
            size_t ko = (size_t)(mb * 128 + row) * DIM + h * 128 + seg * 8;
            uint32_t so = row * 272 + seg * 16;
            cp16(dh + so, Kh + ko);
            cp16(dl + so, Kl + ko);
        }
    };
    auto load_V = [&](int mb) {
#pragma unroll
        for (int u = 0; u < 8; u++) {
            int f = tid + 256 * u;
            int row = f >> 4, seg = f & 15;
            size_t vo = (size_t)(h * 128 + row) * S + mb * 128 + seg * 8;
            uint32_t so = row * 272 + seg * 16;
            cp16(T4 + so, Vth + vo);
            cp16(T5 + so, Vtl + vo);
        }
    };

    if (nc > 0) { load_K(list[pair * 24], T2, T3); CP_COMMIT(); }

    float oacc[16][4];
#pragma unroll
    for (int j = 0; j < 16; j++)
        oacc[j][0] = oacc[j][1] = oacc[j][2] = oacc[j][3] = 0.f;
    float m0 = NEG_BIG, m1 = NEG_BIG, den0 = 0.f, den1 = 0.f;

    for (int b = 0; b < nc; b++) {
        const int mb = list[pair * 24 + b];
        __syncthreads();
        load_V(mb);
        CP_COMMIT();
        CP_WAIT(1);
        __syncthreads();

        const uint32_t kh_b = (b & 1) ? T0 : T2;
        const uint32_t kl_b = (b & 1) ? T1 : T3;

        float sacc[16][4];
#pragma unroll
        for (int j = 0; j < 16; j++)
            sacc[j][0] = sacc[j][1] = sacc[j][2] = sacc[j][3] = 0.f;
#pragma unroll
        for (int ks = 0; ks < 8; ks++) {
#pragma unroll
            for (int jp = 0; jp < 8; jp++) {
                uint32_t kh0, kh1, kh2, kh3, kl0, kl1, kl2, kl3;
                ldsm_x4(kh0, kh1, kh2, kh3, kh_b + b_off + jp * 4352 + ks * 32);
                ldsm_x4(kl0, kl1, kl2, kl3, kl_b + b_off + jp * 4352 + ks * 32);
                mma_bf16(sacc[2 * jp], qfh[ks][0], qfh[ks][1], qfh[ks][2], qfh[ks][3], kh0, kh1);
                mma_bf16(sacc[2 * jp], qfh[ks][0], qfh[ks][1], qfh[ks][2], qfh[ks][3], kl0, kl1);
                mma_bf16(sacc[2 * jp], qfl[ks][0], qfl[ks][1], qfl[ks][2], qfl[ks][3], kh0, kh1);
                mma_bf16(sacc[2 * jp + 1], qfh[ks][0], qfh[ks][1], qfh[ks][2], qfh[ks][3], kh2, kh3);
                mma_bf16(sacc[2 * jp + 1], qfh[ks][0], qfh[ks][1], qfh[ks][2], qfh[ks][3], kl2, kl3);
                mma_bf16(sacc[2 * jp + 1], qfl[ks][0], qfl[ks][1], qfl[ks][2], qfl[ks][3], kh2, kh3);
            }
        }

        float mx0 = NEG_BIG, mx1 = NEG_BIG;
#pragma unroll
        for (int j = 0; j < 16; j++) {
            sacc[j][0] *= SCALE; sacc[j][1] *= SCALE;
            sacc[j][2] *= SCALE; sacc[j][3] *= SCALE;
            mx0 = fmaxf(mx0, fmaxf(sacc[j][0], sacc[j][1]));
            mx1 = fmaxf(mx1, fmaxf(sacc[j][2], sacc[j][3]));
        }
        mx0 = fmaxf(mx0, __shfl_xor_sync(0xffffffffu, mx0, 1));
        mx0 = fmaxf(mx0, __shfl_xor_sync(0xffffffffu, mx0, 2));
        mx1 = fmaxf(mx1, __shfl_xor_sync(0xffffffffu, mx1, 1));
        mx1 = fmaxf(mx1, __shfl_xor_sync(0xffffffffu, mx1, 2));
        float nm0 = fmaxf(m0, mx0), nm1 = fmaxf(m1, mx1);
        float f0 = __expf(m0 - nm0), f1 = __expf(m1 - nm1);
        float rs0 = 0.f, rs1 = 0.f;
#pragma unroll
        for (int j = 0; j < 16; j++) {
            sacc[j][0] = __expf(sacc[j][0] - nm0);
            sacc[j][1] = __expf(sacc[j][1] - nm0);
            sacc[j][2] = __expf(sacc[j][2] - nm1);
            sacc[j][3] = __expf(sacc[j][3] - nm1);
            rs0 += sacc[j][0] + sacc[j][1];
            rs1 += sacc[j][2] + sacc[j][3];
        }
        rs0 += __shfl_xor_sync(0xffffffffu, rs0, 1);
        rs0 += __shfl_xor_sync(0xffffffffu, rs0, 2);
        rs1 += __shfl_xor_sync(0xffffffffu, rs1, 1);
        rs1 += __shfl_xor_sync(0xffffffffu, rs1, 2);
        den0 = den0 * f0 + rs0; m0 = nm0;
        den1 = den1 * f1 + rs1; m1 = nm1;
#pragma unroll
        for (int j = 0; j < 16; j++) {
            oacc[j][0] *= f0; oacc[j][1] *= f0;
            oacc[j][2] *= f1; oacc[j][3] *= f1;
        }

        if (b + 1 < nc) {
            load_K(list[pair * 24 + b + 1], (b & 1) ? T2 : T0, (b & 1) ? T3 : T1);
            CP_COMMIT();
            CP_WAIT(1);
        } else {
            CP_WAIT(0);
        }
        __syncthreads();

#pragma unroll
        for (int kk = 0; kk < 8; kk++) {
            float p00 = sacc[2 * kk][0],     p01 = sacc[2 * kk][1];
            float p10 = sacc[2 * kk][2],     p11 = sacc[2 * kk][3];
            float p20 = sacc[2 * kk + 1][0], p21 = sacc[2 * kk + 1][1];
            float p30 = sacc[2 * kk + 1][2], p31 = sacc[2 * kk + 1][3];
            uint32_t ph0 = pack2(p00, p01), ph1 = pack2(p10, p11);
            uint32_t ph2 = pack2(p20, p21), ph3 = pack2(p30, p31);
            __nv_bfloat162 h0 = *(__nv_bfloat162*)&ph0;
            __nv_bfloat162 h1 = *(__nv_bfloat162*)&ph1;
            __nv_bfloat162 h2 = *(__nv_bfloat162*)&ph2;
            __nv_bfloat162 h3 = *(__nv_bfloat162*)&ph3;
            uint32_t pl0 = pack2(p00 - __bfloat162float(h0.x), p01 - __bfloat162float(h0.y));
            uint32_t pl1 = pack2(p10 - __bfloat162float(h1.x), p11 - __bfloat162float(h1.y));
            uint32_t pl2 = pack2(p20 - __bfloat162float(h2.x), p21 - __bfloat162float(h2.y));
            uint32_t pl3 = pack2(p30 - __bfloat162float(h3.x), p31 - __bfloat162float(h3.y));
#pragma unroll
            for (int jp = 0; jp < 8; jp++) {
                uint32_t vh0, vh1, vh2, vh3, vl0, vl1, vl2, vl3;
                ldsm_x4(vh0, vh1, vh2, vh3, T4 + b_off + jp * 4352 + kk * 32);
                ldsm_x4(vl0, vl1, vl2, vl3, T5 + b_off + jp * 4352 + kk * 32);
                mma_bf16(oacc[2 * jp], ph0, ph1, ph2, ph3, vh0, vh1);
                mma_bf16(oacc[2 * jp], ph0, ph1, ph2, ph3, vl0, vl1);
                mma_bf16(oacc[2 * jp], pl0, pl1, pl2, pl3, vh0, vh1);
                mma_bf16(oacc[2 * jp + 1], ph0, ph1, ph2, ph3, vh2, vh3);
                mma_bf16(oacc[2 * jp + 1], ph0, ph1, ph2, ph3, vl2, vl3);
                mma_bf16(oacc[2 * jp + 1], pl0, pl1, pl2, pl3, vh2, vh3);
            }
        }
    }

    float inv0 = den0 > 0.f ? 1.f / den0 : 0.f;
    float inv1 = den1 > 0.f ? 1.f / den1 : 0.f;
    const int r0 = l * 128 + wid * 16 + g, r1 = r0 + 8;
#pragma unroll
    for (int j = 0; j < 16; j++) {
        int col = h * 128 + j * 8 + 2 * th;
        float v00 = oacc[j][0] * inv0, v01 = oacc[j][1] * inv0;
        float v10 = oacc[j][2] * inv1, v11 = oacc[j][3] * inv1;
        uint32_t h0 = pack2(v00, v01);
        uint32_t h1 = pack2(v10, v11);
        __nv_bfloat162 b0 = *(__nv_bfloat162*)&h0;
        __nv_bfloat162 b1 = *(__nv_bfloat162*)&h1;
        uint32_t l0 = pack2(v00 - __bfloat162float(b0.x), v01 - __bfloat162float(b0.y));
        uint32_t l1 = pack2(v10 - __bfloat162float(b1.x), v11 - __bfloat162float(b1.y));
        *(uint32_t*)(OAh + (size_t)r0 * DIM + col) = h0;
        *(uint32_t*)(OAl + (size_t)r0 * DIM + col) = l0;
        *(uint32_t*)(OAh + (size_t)r1 * DIM + col) = h1;
        *(uint32_t*)(OAl + (size_t)r1 * DIM + col) = l1;
    }
}

// ---------------------------------------------------------------------------
extern "C" void kernel_launch(void* const* d_in, const int* in_sizes, int n_in,
                              void* d_out, int out_size)
{
    const float* x  = (const float*)d_in[0];
    const float* wq = (const float*)d_in[1];
    const float* bq = (const float*)d_in[2];
    const float* wk = (const float*)d_in[3];
    const float* bk = (const float*)d_in[4];
    const float* wv = (const float*)d_in[5];
    const float* bv = (const float*)d_in[6];
    const float* wo = (const float*)d_in[7];
    const float* bo = (const float*)d_in[8];
    const float* gq = (const float*)d_in[9];
    const float* gk = (const float*)d_in[10];
    const float* fc = (const float*)d_in[11];
    const float* fs = (const float*)d_in[12];
    float* out = (float*)d_out;

    float *qp, *kp, *vp, *qwp, *kwp;
    int *lp, *cp, *op;
    cudaGetSymbolAddress((void**)&qp, g_q);
    cudaGetSymbolAddress((void**)&kp, g_k);
    cudaGetSymbolAddress((void**)&vp, g_v);
    cudaGetSymbolAddress((void**)&qwp, g_qw);
    cudaGetSymbolAddress((void**)&kwp, g_kw);
    cudaGetSymbolAddress((void**)&lp, g_list);
    cudaGetSymbolAddress((void**)&cp, g_cnt);
    cudaGetSymbolAddress((void**)&op, g_order);

    __nv_bfloat16 *xh, *xl, *ah, *al;
    __nv_bfloat16 *wqh, *wql, *wkh, *wkl, *wvh, *wvl, *woh, *wol;
    __nv_bfloat16 *qh, *ql, *kh, *kl, *vth, *vtl;
    cudaGetSymbolAddress((void**)&xh, s_xh);
    cudaGetSymbolAddress((void**)&xl, s_xl);
    cudaGetSymbolAddress((void**)&ah, s_ah);
    cudaGetSymbolAddress((void**)&al, s_al);
    cudaGetSymbolAddress((void**)&wqh, s_wqh);
    cudaGetSymbolAddress((void**)&wql, s_wql);
    cudaGetSymbolAddress((void**)&wkh, s_wkh);
    cudaGetSymbolAddress((void**)&wkl, s_wkl);
    cudaGetSymbolAddress((void**)&wvh, s_wvh);
    cudaGetSymbolAddress((void**)&wvl, s_wvl);
    cudaGetSymbolAddress((void**)&woh, s_woh);
    cudaGetSymbolAddress((void**)&wol, s_wol);
    cudaGetSymbolAddress((void**)&qh, s_qh);
    cudaGetSymbolAddress((void**)&ql, s_ql);
    cudaGetSymbolAddress((void**)&kh, s_kh);
    cudaGetSymbolAddress((void**)&kl, s_kl);
    cudaGetSymbolAddress((void**)&vth, s_vth);
    cudaGetSymbolAddress((void**)&vtl, s_vtl);

    cudaFuncSetAttribute(gemm_mma, cudaFuncAttributeMaxDynamicSharedMemorySize, GEMM_SMEM);
    cudaFuncSetAttribute(attn_mma, cudaFuncAttributeMaxDynamicSharedMemorySize, ATT_SMEM);

    // splits (x + weights), vectorized x4
    split_kernel<<<(S * DIM) / 1024, 256>>>(x, xh, xl);
    split_kernel<<<(DIM * DIM) / 1024, 256>>>(wq, wqh, wql);
    split_kernel<<<(DIM * DIM) / 1024, 256>>>(wk, wkh, wkl);
    split_kernel<<<(DIM * DIM) / 1024, 256>>>(wv, wvh, wvl);
    split_kernel<<<(DIM * DIM) / 1024, 256>>>(wo, woh, wol);

    // Q/K/V projections (z-batched), 256x128 tiles
    gemm_mma<<<dim3(12, 12, 3), 512, GEMM_SMEM>>>(
        xh, xl, wqh, wql, wkh, wkl, wvh, wvl, bq, bk, bv, qp, kp, vp);

    norm_rope_kernel<<<dim3(S, 2), 256>>>(qp, kp, qh, ql, kh, kl, gq, gk, fc, fs);
    pool_mean<<<dim3(NB, 2), 256>>>(qp, kp, qwp, kwp);
    select_blocks<<<H, 576>>>(qwp, kwp, lp, cp);
    order_pairs<<<1, NPAIR>>>(cp, op);

    vt_split<<<dim3(S / 32, DIM / 32), 256>>>(vp, vth, vtl);

    attn_mma<<<NPAIR, 256, ATT_SMEM>>>(qh, ql, kh, kl, vth, vtl, lp, cp, op, ah, al);

    // O projection
    gemm_mma<<<dim3(12, 12, 1), 512, GEMM_SMEM>>>(
        ah, al, woh, wol, woh, wol, woh, wol, bo, bo, bo, out, out, out);
}

// round 17
// speedup vs baseline: 1.1334x; 1.1334x over previous
#include <cuda_runtime.h>
#include <cuda_bf16.h>
#include <cuda_fp16.h>
#include <cstdint>

#define S 3072
#define DIM 1536
#define H 12
#define NB 24
#define SCALE 0.08838834764831845f   // 1/sqrt(128)
#define NEG_BIG (-1e30f)
#define NPAIR (H * NB)                // 288

// ---------------- scratch (device globals; no allocation allowed) ----------
__device__ float g_q[S * DIM];
__device__ float g_k[S * DIM];
__device__ float g_v[S * DIM];
__device__ float g_qw[NB * DIM];
__device__ float g_kw[NB * DIM];
__device__ int   g_list[H * NB * NB];
__device__ int   g_cnt[NPAIR];
__device__ int   g_order[NPAIR];

// bf16 hi/lo splits (Q/K path — feeds selection, stays 3-product)
__device__ __nv_bfloat16 s_xh[S * DIM],  s_xl[S * DIM];
__device__ __nv_bfloat16 s_wqh[DIM * DIM], s_wql[DIM * DIM];
__device__ __nv_bfloat16 s_wkh[DIM * DIM], s_wkl[DIM * DIM];
__device__ __nv_bfloat16 s_qh[S * DIM], s_ql[S * DIM];
__device__ __nv_bfloat16 s_kh[S * DIM], s_kl[S * DIM];
// fp16 operands (V / PV / O path — 2-product)
__device__ __half f_xh[S * DIM];                      // x hi only (A-lo dropped)
__device__ __half f_wvh[DIM * DIM], f_wvl[DIM * DIM];
__device__ __half f_woh[DIM * DIM], f_wol[DIM * DIM];
__device__ __half f_vth[DIM * S],  f_vtl[DIM * S];    // transposed [d][t]
__device__ __half f_ah[S * DIM];                      // attention out hi only

// ---------------------------------------------------------------------------
__device__ __forceinline__ uint32_t smem_u32(const void* p) {
    uint32_t a;
    asm("{ .reg .u64 t; cvta.to.shared.u64 t, %1; cvt.u32.u64 %0, t; }"
        : "=r"(a) : "l"(p));
    return a;
}
__device__ __forceinline__ void cp16(uint32_t dst, const void* src) {
    asm volatile("cp.async.cg.shared.global [%0], [%1], 16;" :: "r"(dst), "l"(src));
}
#define CP_COMMIT() asm volatile("cp.async.commit_group;" ::: "memory")
#define CP_WAIT(n)  asm volatile("cp.async.wait_group %0;" :: "n"(n) : "memory")

__device__ __forceinline__ void mma_bf16(float* c, uint32_t a0, uint32_t a1,
                                         uint32_t a2, uint32_t a3,
                                         uint32_t b0, uint32_t b1) {
    asm volatile(
        "mma.sync.aligned.m16n8k16.row.col.f32.bf16.bf16.f32 "
        "{%0,%1,%2,%3}, {%4,%5,%6,%7}, {%8,%9}, {%0,%1,%2,%3};"
        : "+f"(c[0]), "+f"(c[1]), "+f"(c[2]), "+f"(c[3])
        : "r"(a0), "r"(a1), "r"(a2), "r"(a3), "r"(b0), "r"(b1));
}
__device__ __forceinline__ void mma_f16(float* c, uint32_t a0, uint32_t a1,
                                        uint32_t a2, uint32_t a3,
                                        uint32_t b0, uint32_t b1) {
    asm volatile(
        "mma.sync.aligned.m16n8k16.row.col.f32.f16.f16.f32 "
        "{%0,%1,%2,%3}, {%4,%5,%6,%7}, {%8,%9}, {%0,%1,%2,%3};"
        : "+f"(c[0]), "+f"(c[1]), "+f"(c[2]), "+f"(c[3])
        : "r"(a0), "r"(a1), "r"(a2), "r"(a3), "r"(b0), "r"(b1));
}
__device__ __forceinline__ void ldsm_x4(uint32_t& r0, uint32_t& r1,
                                        uint32_t& r2, uint32_t& r3, uint32_t a) {
    asm volatile("ldmatrix.sync.aligned.m8n8.x4.shared.b16 {%0,%1,%2,%3}, [%4];"
                 : "=r"(r0), "=r"(r1), "=r"(r2), "=r"(r3) : "r"(a));
}
__device__ __forceinline__ uint32_t pack2(float x, float y) {
    __nv_bfloat162 t = __floats2bfloat162_rn(x, y);
    return *(uint32_t*)&t;
}
__device__ __forceinline__ uint32_t pack2h(float x, float y) {
    __half2 t = __floats2half2_rn(x, y);
    return *(uint32_t*)&t;
}

// ---------------------------------------------------------------------------
// splits
// ---------------------------------------------------------------------------
__global__ __launch_bounds__(256) void split_kernel(
    const float* __restrict__ X, __nv_bfloat16* __restrict__ Hh,
    __nv_bfloat16* __restrict__ Hl)
{
    int i = (blockIdx.x * 256 + threadIdx.x) * 4;
    float4 v = *(const float4*)(X + i);
    uint32_t h0 = pack2(v.x, v.y), h1 = pack2(v.z, v.w);
    __nv_bfloat162 b0 = *(__nv_bfloat162*)&h0;
    __nv_bfloat162 b1 = *(__nv_bfloat162*)&h1;
    uint32_t l0 = pack2(v.x - __bfloat162float(b0.x), v.y - __bfloat162float(b0.y));
    uint32_t l1 = pack2(v.z - __bfloat162float(b1.x), v.w - __bfloat162float(b1.y));
    *(uint32_t*)(Hh + i) = h0;  *(uint32_t*)(Hh + i + 2) = h1;
    *(uint32_t*)(Hl + i) = l0;  *(uint32_t*)(Hl + i + 2) = l1;
}

__global__ __launch_bounds__(256) void split_kernel_h(
    const float* __restrict__ X, __half* __restrict__ Hh,
    __half* __restrict__ Hl)
{
    int i = (blockIdx.x * 256 + threadIdx.x) * 4;
    float4 v = *(const float4*)(X + i);
    uint32_t h0 = pack2h(v.x, v.y), h1 = pack2h(v.z, v.w);
    __half2 b0 = *(__half2*)&h0;
    __half2 b1 = *(__half2*)&h1;
    uint32_t l0 = pack2h(v.x - __half2float(b0.x), v.y - __half2float(b0.y));
    uint32_t l1 = pack2h(v.z - __half2float(b1.x), v.w - __half2float(b1.y));
    *(uint32_t*)(Hh + i) = h0;  *(uint32_t*)(Hh + i + 2) = h1;
    *(uint32_t*)(Hl + i) = l0;  *(uint32_t*)(Hl + i + 2) = l1;
}

__global__ __launch_bounds__(256) void split_hi_h(
    const float* __restrict__ X, __half* __restrict__ Hh)
{
    int i = (blockIdx.x * 256 + threadIdx.x) * 4;
    float4 v = *(const float4*)(X + i);
    uint32_t h0 = pack2h(v.x, v.y), h1 = pack2h(v.z, v.w);
    *(uint32_t*)(Hh + i) = h0;  *(uint32_t*)(Hh + i + 2) = h1;
}

// ---------------------------------------------------------------------------
__global__ __launch_bounds__(256) void vt_split(
    const float* __restrict__ V, __half* __restrict__ Th,
    __half* __restrict__ Tl)
{
    __shared__ float tile[32][33];
    const int t0 = blockIdx.x * 32, d0 = blockIdx.y * 32;
    const int tx = threadIdx.x & 31, ty = threadIdx.x >> 5;
#pragma unroll
    for (int i = 0; i < 4; i++)
        tile[ty + 8 * i][tx] = V[(size_t)(t0 + ty + 8 * i) * DIM + d0 + tx];
    __syncthreads();
#pragma unroll
    for (int i = 0; i < 4; i++) {
        float v = tile[tx][ty + 8 * i];
        __half h = __float2half_rn(v);
        size_t o = (size_t)(d0 + ty + 8 * i) * S + t0 + tx;
        Th[o] = h;
        Tl[o] = __float2half_rn(v - __half2float(h));
    }
}

// ---------------------------------------------------------------------------
// mma.sync GEMM template: F16=false -> bf16 3-product; F16=true -> fp16
// 2-product (A-lo never loaded). 256x128 CTA, 512 thr, 2-stage.
// ---------------------------------------------------------------------------
#define GTILEA 36864                  // 256 rows * 144B
#define GTILEB 18432                  // 128 rows * 144B
#define GSTAGE (2 * GTILEA + 2 * GTILEB)   // 110592
#define GEMM_SMEM (2 * GSTAGE)             // 221184

template<bool F16>
__global__ __launch_bounds__(512, 1) void gemm_mma(
    const __nv_bfloat16* __restrict__ Ah, const __nv_bfloat16* __restrict__ Al,
    const __nv_bfloat16* __restrict__ Wh0, const __nv_bfloat16* __restrict__ Wl0,
    const __nv_bfloat16* __restrict__ Wh1, const __nv_bfloat16* __restrict__ Wl1,
    const float* __restrict__ b0, const float* __restrict__ b1,
    float* __restrict__ C0, float* __restrict__ C1)
{
    extern __shared__ char smem[];
    const int z = blockIdx.z;
    const __nv_bfloat16* Wh = z == 0 ? Wh0 : Wh1;
    const __nv_bfloat16* Wl = z == 0 ? Wl0 : Wl1;
    const float* bias = z == 0 ? b0 : b1;
    float* C = z == 0 ? C0 : C1;

    const int n0 = blockIdx.x * 128;
    const int m0 = blockIdx.y * 256;
    const int tid = threadIdx.x;
    const int lane = tid & 31, wid = tid >> 5;
    const int warp_m = wid & 3, warp_n = wid >> 2;
    const int g = lane >> 2, th = lane & 3;
    const int lidx = lane >> 3, lrow = lane & 7;

    const uint32_t sbase = smem_u32(smem);
    const uint32_t ga_off = (uint32_t)(warp_m * 64 + lrow + ((lane >> 3) & 1) * 8) * 144
                          + ((lane >> 4) & 1) * 16;
    const uint32_t gb_off = (uint32_t)(warp_n * 32 + lrow + (lidx >> 1) * 8) * 144
                          + (lidx & 1) * 16;

    auto load_stage = [&](int stage, int c) {
        uint32_t stb = sbase + stage * GSTAGE;
        const __nv_bfloat16* ah = Ah + (size_t)m0 * DIM + c * 64;
        const __nv_bfloat16* al = Al + (size_t)m0 * DIM + c * 64;
        const __nv_bfloat16* wh = Wh + (size_t)n0 * DIM + c * 64;
        const __nv_bfloat16* wl = Wl + (size_t)n0 * DIM + c * 64;
#pragma unroll
        for (int u = 0; u < 4; u++) {
            int f = tid + 512 * u;
            int row = f >> 3, seg = f & 7;
            cp16(stb + row * 144 + seg * 16, ah + (size_t)row * DIM + seg * 8);
            if (!F16)
                cp16(stb + GTILEA + row * 144 + seg * 16, al + (size_t)row * DIM + seg * 8);
        }
#pragma unroll
        for (int u = 0; u < 2; u++) {
            int f = tid + 512 * u;
            int row = f >> 3, seg = f & 7;
            cp16(stb + 2 * GTILEA + row * 144 + seg * 16, wh + (size_t)row * DIM + seg * 8);
            cp16(stb + 2 * GTILEA + GTILEB + row * 144 + seg * 16, wl + (size_t)row * DIM + seg * 8);
        }
    };

    float acc[4][4][4];
#pragma unroll
    for (int i = 0; i < 4; i++)
#pragma unroll
        for (int j = 0; j < 4; j++)
#pragma unroll
            for (int r = 0; r < 4; r++) acc[i][j][r] = 0.f;

    load_stage(0, 0); CP_COMMIT();

    for (int c = 0; c < 24; c++) {
        if (c + 1 < 24) { load_stage((c + 1) & 1, c + 1); CP_COMMIT(); CP_WAIT(1); }
        else            { CP_WAIT(0); }
        __syncthreads();

        const uint32_t stg = sbase + (c & 1) * GSTAGE;
        const uint32_t sAh = stg, sAl = stg + GTILEA;
        const uint32_t sWh = stg + 2 * GTILEA, sWl = stg + 2 * GTILEA + GTILEB;

#pragma unroll
        for (int ks = 0; ks < 4; ks++) {
            uint32_t bh[8], bl[8];
            ldsm_x4(bh[0], bh[1], bh[2], bh[3], sWh + gb_off + ks * 32);
            ldsm_x4(bh[4], bh[5], bh[6], bh[7], sWh + gb_off + 2304 + ks * 32);
            ldsm_x4(bl[0], bl[1], bl[2], bl[3], sWl + gb_off + ks * 32);
            ldsm_x4(bl[4], bl[5], bl[6], bl[7], sWl + gb_off + 2304 + ks * 32);
#pragma unroll
            for (int mt = 0; mt < 4; mt++) {
                uint32_t a0, a1, a2, a3;
                ldsm_x4(a0, a1, a2, a3, sAh + ga_off + mt * 2304 + ks * 32);
                uint32_t c0 = 0, c1 = 0, c2 = 0, c3 = 0;
                if (!F16) ldsm_x4(c0, c1, c2, c3, sAl + ga_off + mt * 2304 + ks * 32);
#pragma unroll
                for (int j = 0; j < 4; j++) {
                    if (F16) {
                        mma_f16(acc[mt][j], a0, a1, a2, a3, bh[2 * j], bh[2 * j + 1]);
                        mma_f16(acc[mt][j], a0, a1, a2, a3, bl[2 * j], bl[2 * j + 1]);
                    } else {
                        mma_bf16(acc[mt][j], a0, a1, a2, a3, bh[2 * j], bh[2 * j + 1]);
                        mma_bf16(acc[mt][j], a0, a1, a2, a3, bl[2 * j], bl[2 * j + 1]);
                        mma_bf16(acc[mt][j], c0, c1, c2, c3, bh[2 * j], bh[2 * j + 1]);
                    }
                }
            }
        }
        __syncthreads();
    }

#pragma unroll
    for (int mt = 0; mt < 4; mt++) {
        int r = m0 + warp_m * 64 + mt * 16 + g;
#pragma unroll
        for (int j = 0; j < 4; j++) {
            int col = n0 + warp_n * 32 + j * 8 + th * 2;
            float bx = bias[col], by = bias[col + 1];
            float2 o0 = { acc[mt][j][0] + bx, acc[mt][j][1] + by };
            float2 o1 = { acc[mt][j][2] + bx, acc[mt][j][3] + by };
            *(float2*)(C + (size_t)r * DIM + col) = o0;
            *(float2*)(C + (size_t)(r + 8) * DIM + col) = o1;
        }
    }
}

// ---------------------------------------------------------------------------
// RMSNorm + RoPE, fused bf16 hi/lo split output
// ---------------------------------------------------------------------------
__global__ __launch_bounds__(256) void norm_rope_kernel(
    float* __restrict__ Xq, float* __restrict__ Xk,
    __nv_bfloat16* __restrict__ Qh, __nv_bfloat16* __restrict__ Ql,
    __nv_bfloat16* __restrict__ Kh, __nv_bfloat16* __restrict__ Kl,
    const float* __restrict__ gq, const float* __restrict__ gk,
    const float* __restrict__ fc, const float* __restrict__ fs)
{
    const int s = blockIdx.x;
    float* X = blockIdx.y ? Xk : Xq;
    __nv_bfloat16* Oh = blockIdx.y ? Kh : Qh;
    __nv_bfloat16* Ol = blockIdx.y ? Kl : Ql;
    const float* g = blockIdx.y ? gk : gq;
    float* row = X + (size_t)s * 1536;
    const int tid = threadIdx.x;

    float ss = 0.f;
#pragma unroll
    for (int c = 0; c < 6; c++) {
        float v = row[tid + 256 * c];
        ss += v * v;
    }
#pragma unroll
    for (int o = 16; o >= 1; o >>= 1)
        ss += __shfl_xor_sync(0xffffffffu, ss, o);
    __shared__ float red[8];
    if ((tid & 31) == 0) red[tid >> 5] = ss;
    __syncthreads();
    float tot = 0.f;
#pragma unroll
    for (int w = 0; w < 8; w++) tot += red[w];
    float scale = rsqrtf(tot * (1.f / 1536.f) + 1e-5f);

#pragma unroll
    for (int u = 0; u < 3; u++) {
        int p = tid + 256 * u;
        int i = p & 63;
        float c = fc[s * 64 + i];
        float sn = fs[s * 64 + i];
        float x0 = row[2 * p] * scale * g[2 * p];
        float x1 = row[2 * p + 1] * scale * g[2 * p + 1];
        float y0 = x0 * c - x1 * sn;
        float y1 = x0 * sn + x1 * c;
        row[2 * p]     = y0;
        row[2 * p + 1] = y1;
        size_t o = (size_t)s * 1536 + 2 * p;
        __nv_bfloat16 h0 = __float2bfloat16(y0);
        __nv_bfloat16 h1 = __float2bfloat16(y1);
        Oh[o] = h0;     Oh[o + 1] = h1;
        Ol[o] = __float2bfloat16(y0 - __bfloat162float(h0));
        Ol[o + 1] = __float2bfloat16(y1 - __bfloat162float(h1));
    }
}

// ---------------------------------------------------------------------------
__global__ __launch_bounds__(256) void pool_mean(
    const float* __restrict__ Q, const float* __restrict__ Kx,
    float* __restrict__ qw, float* __restrict__ kw)
{
    const int nb = blockIdx.x;
    const float* X = blockIdx.y ? Kx : Q;
    float* Wo = blockIdx.y ? kw : qw;
    const int tid = threadIdx.x;
    float acc[6] = {0, 0, 0, 0, 0, 0};
    for (int t = 0; t < 128; t++) {
        const float* row = X + (size_t)(nb * 128 + t) * 1536;
#pragma unroll
        for (int c = 0; c < 6; c++) acc[c] += row[tid + 256 * c];
    }
#pragma unroll
    for (int c = 0; c < 6; c++)
        Wo[nb * 1536 + tid + 256 * c] = acc[c] * (1.f / 128.f);
}

// ---------------------------------------------------------------------------
// select_blocks: fused draft scores + row softmax + top-k threshold + lists
// ---------------------------------------------------------------------------
__global__ __launch_bounds__(576) void select_blocks(
    const float* __restrict__ qw, const float* __restrict__ kw,
    int* __restrict__ list, int* __restrict__ cnt)
{
    const int h = blockIdx.x;
    __shared__ float qb[24 * 128];
    __shared__ float kb[24 * 128];
    __shared__ float sbuf[576];
    __shared__ float battn[576];
    __shared__ float result;
    const int tid = threadIdx.x;
    const int l = tid / 24, m = tid % 24;

    for (int i = tid; i < 24 * 128; i += 576) {
        int r = i >> 7, d = i & 127;
        qb[i] = qw[r * 1536 + h * 128 + d];
        kb[i] = kw[r * 1536 + h * 128 + d];
    }
    if (tid == 0) result = 0.f;
    __syncthreads();

    int rl = l >> 2, cl = l & 3, rm = m >> 2, cm = m & 3;
    bool ok = (rm >= rl - 3) && (rm <= rl + 2) && (cm >= cl - 3) && (cm <= cl + 2);
    float sc = NEG_BIG;
    if (ok) {
        float sum = 0.f;
        const float* qr = qb + l * 128;
        const float* kr = kb + m * 128;
#pragma unroll 8
        for (int d = 0; d < 128; d++) sum += qr[d] * kr[d];
        sc = sum * SCALE;
    }
    sbuf[tid] = sc;
    __syncthreads();

    float mx = NEG_BIG;
#pragma unroll
    for (int j = 0; j < 24; j++) mx = fmaxf(mx, sbuf[l * 24 + j]);
    float e = __expf(sc - mx);
    battn[tid] = e;
    __syncthreads();
    float se = 0.f;
#pragma unroll
    for (int j = 0; j < 24; j++) se += battn[l * 24 + j];
    __syncthreads();
    float p = e / se;
    battn[tid] = p;
    __syncthreads();

    {
        int cg = 0, ce = 0;
        for (int x = 0; x < 576; x++) {
            cg += (battn[x] > p);
            ce += (battn[x] == p);
        }
        if (cg <= 128 && cg + ce >= 129) result = p;
    }
    __syncthreads();
    float thr = result;

    if (tid < 24) {
        int pos = 0;
        for (int mm = 0; mm < 24; mm++) {
            if (battn[tid * 24 + mm] > thr)
                list[(h * 24 + tid) * 24 + pos++] = mm;
        }
        cnt[h * 24 + tid] = pos;
    }
}

// ---------------------------------------------------------------------------
__global__ void order_pairs(const int* __restrict__ cnt, int* __restrict__ order)
{
    __shared__ int bucket[32];
    __shared__ int base[32];
    const int tid = threadIdx.x;
    if (tid < 32) bucket[tid] = 0;
    __syncthreads();
    int nc = cnt[tid];
    atomicAdd(&bucket[nc], 1);
    __syncthreads();
    if (tid == 0) {
        int acc = 0;
        for (int v = 31; v >= 0; v--) { base[v] = acc; acc += bucket[v]; }
    }
    __syncthreads();
    int pos = atomicAdd(&base[nc], 1);
    order[pos] = tid;
}

// ---------------------------------------------------------------------------
// Block-sparse flash attention: S = bf16 3-product (Q frags in regs),
// PV = fp16 2-product (P hi only); pipelined K/V loads; fp16-hi output.
// ---------------------------------------------------------------------------
#define AT_U32 68
#define AT_TILEB (128 * AT_U32 * 4)     // 34816
#define ATT_SMEM (6 * AT_TILEB)         // 208896

__global__ __launch_bounds__(256, 1) void attn_mma(
    const __nv_bfloat16* __restrict__ Qh, const __nv_bfloat16* __restrict__ Ql,
    const __nv_bfloat16* __restrict__ Kh, const __nv_bfloat16* __restrict__ Kl,
    const __half* __restrict__ Vth, const __half* __restrict__ Vtl,
    const int* __restrict__ list, const int* __restrict__ cnt,
    const int* __restrict__ order,
    __half* __restrict__ OAh)
{
    extern __shared__ char smem[];
    const int pair = order[blockIdx.x];
    const int h = pair / 24, l = pair % 24;
    const int tid = threadIdx.x;
    const int lane = tid & 31, wid = tid >> 5;
    const int g = lane >> 2, th = lane & 3;
    const int lidx = lane >> 3, lrow = lane & 7;
    const uint32_t sb = smem_u32(smem);
    const uint32_t T0 = sb,               T1 = sb + AT_TILEB;
    const uint32_t T2 = sb + 2 * AT_TILEB, T3 = sb + 3 * AT_TILEB;
    const uint32_t T4 = sb + 4 * AT_TILEB, T5 = sb + 5 * AT_TILEB;

    const uint32_t a_off = (uint32_t)(wid * 16 + lrow + ((lane >> 3) & 1) * 8) * 272
                         + ((lane >> 4) & 1) * 16;
    const uint32_t b_off = (uint32_t)(lrow + (lidx >> 1) * 8) * 272 + (lidx & 1) * 16;

    // ---- stage Q into T0/T1, pull fragments into registers ----
#pragma unroll
    for (int t = 0; t < 2; t++) {
        const __nv_bfloat16* src = t ? Ql : Qh;
        uint32_t dst = t ? T1 : T0;
#pragma unroll
        for (int u = 0; u < 8; u++) {
            int f = tid + 256 * u;
            int row = f >> 4, seg = f & 15;
            cp16(dst + row * 272 + seg * 16,
                 src + (size_t)(l * 128 + row) * DIM + h * 128 + seg * 8);
        }
    }
    CP_COMMIT();
    CP_WAIT(0);
    __syncthreads();

    uint32_t qfh[8][4], qfl[8][4];
#pragma unroll
    for (int ks = 0; ks < 8; ks++) {
        ldsm_x4(qfh[ks][0], qfh[ks][1], qfh[ks][2], qfh[ks][3], T0 + a_off + ks * 32);
        ldsm_x4(qfl[ks][0], qfl[ks][1], qfl[ks][2], qfl[ks][3], T1 + a_off + ks * 32);
    }
    __syncthreads();

    const int nc = cnt[pair];

    auto load_K = [&](int mb, uint32_t dh, uint32_t dl) {
#pragma unroll
        for (int u = 0; u < 8; u++) {
            int f = tid + 256 * u;
            int row = f >> 4, seg = f & 15;
            size_t ko = (size_t)(mb * 128 + row) * DIM + h * 128 + seg * 8;
            uint32_t so = row * 272 + seg * 16;
            cp16(dh + so, Kh + ko);
            cp16(dl + so, Kl + ko);
        }
    };
    auto load_V = [&](int mb) {
#pragma unroll
        for (int u = 0; u < 8; u++) {
            int f = tid + 256 * u;
            int row = f >> 4, seg = f & 15;
            size_t vo = (size_t)(h * 128 + row) * S + mb * 128 + seg * 8;
            uint32_t so = row * 272 + seg * 16;
            cp16(T4 + so, Vth + vo);
            cp16(T5 + so, Vtl + vo);
        }
    };

    if (nc > 0) { load_K(list[pair * 24], T2, T3); CP_COMMIT(); }

    float oacc[16][4];
#pragma unroll
    for (int j = 0; j < 16; j++)
        oacc[j][0] = oacc[j][1] = oacc[j][2] = oacc[j][3] = 0.f;
    float m0 = NEG_BIG, m1 = NEG_BIG, den0 = 0.f, den1 = 0.f;

    for (int b = 0; b < nc; b++) {
        const int mb = list[pair * 24 + b];
        __syncthreads();
        load_V(mb);
        CP_COMMIT();
        CP_WAIT(1);
        __syncthreads();

        const uint32_t kh_b = (b & 1) ? T0 : T2;
        const uint32_t kl_b = (b & 1) ? T1 : T3;

        float sacc[16][4];
#pragma unroll
        for (int j = 0; j < 16; j++)
            sacc[j][0] = sacc[j][1] = sacc[j][2] = sacc[j][3] = 0.f;
#pragma unroll
        for (int ks = 0; ks < 8; ks++) {
#pragma unroll
            for (int jp = 0; jp < 8; jp++) {
                uint32_t kh0, kh1, kh2, kh3, kl0, kl1, kl2, kl3;
                ldsm_x4(kh0, kh1, kh2, kh3, kh_b + b_off + jp * 4352 + ks * 32);
                ldsm_x4(kl0, kl1, kl2, kl3, kl_b + b_off + jp * 4352 + ks * 32);
                mma_bf16(sacc[2 * jp], qfh[ks][0], qfh[ks][1], qfh[ks][2], qfh[ks][3], kh0, kh1);
                mma_bf16(sacc[2 * jp], qfh[ks][0], qfh[ks][1], qfh[ks][2], qfh[ks][3], kl0, kl1);
                mma_bf16(sacc[2 * jp], qfl[ks][0], qfl[ks][1], qfl[ks][2], qfl[ks][3], kh0, kh1);
                mma_bf16(sacc[2 * jp + 1], qfh[ks][0], qfh[ks][1], qfh[ks][2], qfh[ks][3], kh2, kh3);
                mma_bf16(sacc[2 * jp + 1], qfh[ks][0], qfh[ks][1], qfh[ks][2], qfh[ks][3], kl2, kl3);
                mma_bf16(sacc[2 * jp + 1], qfl[ks][0], qfl[ks][1], qfl[ks][2], qfl[ks][3], kh2, kh3);
            }
        }

        float mx0 = NEG_BIG, mx1 = NEG_BIG;
#pragma unroll
        for (int j = 0; j < 16; j++) {
            sacc[j][0] *= SCALE; sacc[j][1] *= SCALE;
            sacc[j][2] *= SCALE; sacc[j][3] *= SCALE;
            mx0 = fmaxf(mx0, fmaxf(sacc[j][0], sacc[j][1]));
            mx1 = fmaxf(mx1, fmaxf(sacc[j][2], sacc[j][3]));
        }
        mx0 = fmaxf(mx0, __shfl_xor_sync(0xffffffffu, mx0, 1));
        mx0 = fmaxf(mx0, __shfl_xor_sync(0xffffffffu, mx0, 2));
        mx1 = fmaxf(mx1, __shfl_xor_sync(0xffffffffu, mx1, 1));
        mx1 = fmaxf(mx1, __shfl_xor_sync(0xffffffffu, mx1, 2));
        float nm0 = fmaxf(m0, mx0), nm1 = fmaxf(m1, mx1);
        float f0 = __expf(m0 - nm0), f1 = __expf(m1 - nm1);
        float rs0 = 0.f, rs1 = 0.f;
#pragma unroll
        for (int j = 0; j < 16; j++) {
            sacc[j][0] = __expf(sacc[j][0] - nm0);
            sacc[j][1] = __expf(sacc[j][1] - nm0);
            sacc[j][2] = __expf(sacc[j][2] - nm1);
            sacc[j][3] = __expf(sacc[j][3] - nm1);
            rs0 += sacc[j][0] + sacc[j][1];
            rs1 += sacc[j][2] + sacc[j][3];
        }
        rs0 += __shfl_xor_sync(0xffffffffu, rs0, 1);
        rs0 += __shfl_xor_sync(0xffffffffu, rs0, 2);
        rs1 += __shfl_xor_sync(0xffffffffu, rs1, 1);
        rs1 += __shfl_xor_sync(0xffffffffu, rs1, 2);
        den0 = den0 * f0 + rs0; m0 = nm0;
        den1 = den1 * f1 + rs1; m1 = nm1;
#pragma unroll
        for (int j = 0; j < 16; j++) {
            oacc[j][0] *= f0; oacc[j][1] *= f0;
            oacc[j][2] *= f1; oacc[j][3] *= f1;
        }

        if (b + 1 < nc) {
            load_K(list[pair * 24 + b + 1], (b & 1) ? T2 : T0, (b & 1) ? T3 : T1);
            CP_COMMIT();
            CP_WAIT(1);
        } else {
            CP_WAIT(0);
        }
        __syncthreads();

        // ---- O += P V  (fp16 2-product: P hi only) ----
#pragma unroll
        for (int kk = 0; kk < 8; kk++) {
            uint32_t ph0 = pack2h(sacc[2 * kk][0],     sacc[2 * kk][1]);
            uint32_t ph1 = pack2h(sacc[2 * kk][2],     sacc[2 * kk][3]);
            uint32_t ph2 = pack2h(sacc[2 * kk + 1][0], sacc[2 * kk + 1][1]);
            uint32_t ph3 = pack2h(sacc[2 * kk + 1][2], sacc[2 * kk + 1][3]);
#pragma unroll
            for (int jp = 0; jp < 8; jp++) {
                uint32_t vh0, vh1, vh2, vh3, vl0, vl1, vl2, vl3;
                ldsm_x4(vh0, vh1, vh2, vh3, T4 + b_off + jp * 4352 + kk * 32);
                ldsm_x4(vl0, vl1, vl2, vl3, T5 + b_off + jp * 4352 + kk * 32);
                mma_f16(oacc[2 * jp], ph0, ph1, ph2, ph3, vh0, vh1);
                mma_f16(oacc[2 * jp], ph0, ph1, ph2, ph3, vl0, vl1);
                mma_f16(oacc[2 * jp + 1], ph0, ph1, ph2, ph3, vh2, vh3);
                mma_f16(oacc[2 * jp + 1], ph0, ph1, ph2, ph3, vl2, vl3);
            }
        }
    }

    // epilogue: normalize + fp16 hi write
    float inv0 = den0 > 0.f ? 1.f / den0 : 0.f;
    float inv1 = den1 > 0.f ? 1.f / den1 : 0.f;
    const int r0 = l * 128 + wid * 16 + g, r1 = r0 + 8;
#pragma unroll
    for (int j = 0; j < 16; j++) {
        int col = h * 128 + j * 8 + 2 * th;
        uint32_t h0 = pack2h(oacc[j][0] * inv0, oacc[j][1] * inv0);
        uint32_t h1 = pack2h(oacc[j][2] * inv1, oacc[j][3] * inv1);
        *(uint32_t*)(OAh + (size_t)r0 * DIM + col) = h0;
        *(uint32_t*)(OAh + (size_t)r1 * DIM + col) = h1;
    }
}

// ---------------------------------------------------------------------------
extern "C" void kernel_launch(void* const* d_in, const int* in_sizes, int n_in,
                              void* d_out, int out_size)
{
    const float* x  = (const float*)d_in[0];
    const float* wq = (const float*)d_in[1];
    const float* bq = (const float*)d_in[2];
    const float* wk = (const float*)d_in[3];
    const float* bk = (const float*)d_in[4];
    const float* wv = (const float*)d_in[5];
    const float* bv = (const float*)d_in[6];
    const float* wo = (const float*)d_in[7];
    const float* bo = (const float*)d_in[8];
    const float* gq = (const float*)d_in[9];
    const float* gk = (const float*)d_in[10];
    const float* fc = (const float*)d_in[11];
    const float* fs = (const float*)d_in[12];
    float* out = (float*)d_out;

    float *qp, *kp, *vp, *qwp, *kwp;
    int *lp, *cp, *op;
    cudaGetSymbolAddress((void**)&qp, g_q);
    cudaGetSymbolAddress((void**)&kp, g_k);
    cudaGetSymbolAddress((void**)&vp, g_v);
    cudaGetSymbolAddress((void**)&qwp, g_qw);
    cudaGetSymbolAddress((void**)&kwp, g_kw);
    cudaGetSymbolAddress((void**)&lp, g_list);
    cudaGetSymbolAddress((void**)&cp, g_cnt);
    cudaGetSymbolAddress((void**)&op, g_order);

    __nv_bfloat16 *xh, *xl, *wqh, *wql, *wkh, *wkl, *qh, *ql, *kh, *kl;
    __half *fxh, *fwvh, *fwvl, *fwoh, *fwol, *fvth, *fvtl, *fah;
    cudaGetSymbolAddress((void**)&xh, s_xh);
    cudaGetSymbolAddress((void**)&xl, s_xl);
    cudaGetSymbolAddress((void**)&wqh, s_wqh);
    cudaGetSymbolAddress((void**)&wql, s_wql);
    cudaGetSymbolAddress((void**)&wkh, s_wkh);
    cudaGetSymbolAddress((void**)&wkl, s_wkl);
    cudaGetSymbolAddress((void**)&qh, s_qh);
    cudaGetSymbolAddress((void**)&ql, s_ql);
    cudaGetSymbolAddress((void**)&kh, s_kh);
    cudaGetSymbolAddress((void**)&kl, s_kl);
    cudaGetSymbolAddress((void**)&fxh, f_xh);
    cudaGetSymbolAddress((void**)&fwvh, f_wvh);
    cudaGetSymbolAddress((void**)&fwvl, f_wvl);
    cudaGetSymbolAddress((void**)&fwoh, f_woh);
    cudaGetSymbolAddress((void**)&fwol, f_wol);
    cudaGetSymbolAddress((void**)&fvth, f_vth);
    cudaGetSymbolAddress((void**)&fvtl, f_vtl);
    cudaGetSymbolAddress((void**)&fah, f_ah);

    cudaFuncSetAttribute(gemm_mma<false>, cudaFuncAttributeMaxDynamicSharedMemorySize, GEMM_SMEM);
    cudaFuncSetAttribute(gemm_mma<true>, cudaFuncAttributeMaxDynamicSharedMemorySize, GEMM_SMEM);
    cudaFuncSetAttribute(attn_mma, cudaFuncAttributeMaxDynamicSharedMemorySize, ATT_SMEM);

    // splits
    split_kernel<<<(S * DIM) / 1024, 256>>>(x, xh, xl);
    split_hi_h<<<(S * DIM) / 1024, 256>>>(x, fxh);
    split_kernel<<<(DIM * DIM) / 1024, 256>>>(wq, wqh, wql);
    split_kernel<<<(DIM * DIM) / 1024, 256>>>(wk, wkh, wkl);
    split_kernel_h<<<(DIM * DIM) / 1024, 256>>>(wv, fwvh, fwvl);
    split_kernel_h<<<(DIM * DIM) / 1024, 256>>>(wo, fwoh, fwol);

    // Q/K projections (bf16 3-product, z-batched)
    gemm_mma<false><<<dim3(12, 12, 2), 512, GEMM_SMEM>>>(
        xh, xl, wqh, wql, wkh, wkl, bq, bk, qp, kp);
    // V projection (fp16 2-product)
    gemm_mma<true><<<dim3(12, 12, 1), 512, GEMM_SMEM>>>(
        (const __nv_bfloat16*)fxh, (const __nv_bfloat16*)fxh,
        (const __nv_bfloat16*)fwvh, (const __nv_bfloat16*)fwvl,
        (const __nv_bfloat16*)fwvh, (const __nv_bfloat16*)fwvl,
        bv, bv, vp, vp);

    norm_rope_kernel<<<dim3(S, 2), 256>>>(qp, kp, qh, ql, kh, kl, gq, gk, fc, fs);
    pool_mean<<<dim3(NB, 2), 256>>>(qp, kp, qwp, kwp);
    select_blocks<<<H, 576>>>(qwp, kwp, lp, cp);
    order_pairs<<<1, NPAIR>>>(cp, op);

    vt_split<<<dim3(S / 32, DIM / 32), 256>>>(vp, fvth, fvtl);

    attn_mma<<<NPAIR, 256, ATT_SMEM>>>(qh, ql, kh, kl, fvth, fvtl, lp, cp, op, fah);

    // O projection (fp16 2-product)
    gemm_mma<true><<<dim3(12, 12, 1), 512, GEMM_SMEM>>>(
        (const __nv_bfloat16*)fah, (const __nv_bfloat16*)fah,
        (const __nv_bfloat16*)fwoh, (const __nv_bfloat16*)fwol,
        (const __nv_bfloat16*)fwoh, (const __nv_bfloat16*)fwol,
        bo, bo, out, out);
}